// round 12
// baseline (speedup 1.0000x reference)
#include <cuda_runtime.h>
#include <cuda_bf16.h>
#include <cstddef>

#define N_NODES 100000
#define N_EDGES 1600000
#define N_FEAT  128
#define H_CH    64
#define N_GRAPHS 4096

// ---------------------------------------------------------------------------
// Scratch (device globals; no allocation allowed)
// ---------------------------------------------------------------------------
__device__ int   g_cnt_i[N_NODES];                  // per-dst edge count
__device__ int   g_off  [N_NODES + 1];              // CSR offsets (exclusive scan)
__device__ int   g_pos  [N_NODES];                  // scatter cursors
__device__ int   g_srcs [N_EDGES];                  // src indices grouped by dst
__device__ float g_dinv [N_NODES];
__device__ float g_hw  [(size_t)N_NODES * H_CH];    // pre-scaled message: (h@W)*dinv[n]
__device__ float g_agg [(size_t)N_NODES * H_CH];    // pre-scale-domain accumulator
__device__ float g_hs  [(size_t)N_NODES * H_CH];    // skip-path result
__device__ float g_pool[(size_t)N_GRAPHS * H_CH];
__device__ float g_cnt [N_GRAPHS];

// ---------------------------------------------------------------------------
// Prep kernels: histogram -> dinv -> scan -> scatter (CSR by dst)
// ---------------------------------------------------------------------------
__global__ void zero_f_kernel(float* __restrict__ p, int n) {
    int i = blockIdx.x * blockDim.x + threadIdx.x;
    if (i < n) p[i] = 0.f;
}

__global__ void zero_i_kernel(int* __restrict__ p, int n) {
    int i = blockIdx.x * blockDim.x + threadIdx.x;
    if (i < n) p[i] = 0;
}

__global__ void hist_kernel(const int* __restrict__ dst) {
    int i = blockIdx.x * blockDim.x + threadIdx.x;
    if (i < N_EDGES) atomicAdd(&g_cnt_i[dst[i]], 1);
}

__global__ void dinv_kernel() {
    int i = blockIdx.x * blockDim.x + threadIdx.x;
    if (i < N_NODES) g_dinv[i] = rsqrtf((float)g_cnt_i[i] + 1.0f);
}

// One-block exclusive scan of g_cnt_i -> g_off (and g_pos copy).
__global__ void __launch_bounds__(1024) scan_kernel() {
    const int T = 1024;
    const int C = (N_NODES + T - 1) / T;   // 98 elems per thread
    __shared__ int tsum[T];
    int tid = threadIdx.x;
    int base = tid * C;

    int s = 0;
    for (int j = 0; j < C; j++) {
        int i = base + j;
        if (i < N_NODES) s += g_cnt_i[i];
    }
    tsum[tid] = s;
    __syncthreads();

    // Hillis-Steele inclusive scan over 1024 thread sums
    for (int off = 1; off < T; off <<= 1) {
        int v = (tid >= off) ? tsum[tid - off] : 0;
        __syncthreads();
        tsum[tid] += v;
        __syncthreads();
    }

    int run = (tid > 0) ? tsum[tid - 1] : 0;   // exclusive base
    for (int j = 0; j < C; j++) {
        int i = base + j;
        if (i < N_NODES) {
            g_off[i] = run;
            g_pos[i] = run;
            run += g_cnt_i[i];
        }
    }
    if (tid == 0) g_off[N_NODES] = N_EDGES;
}

__global__ void scatter_kernel(const int* __restrict__ src, const int* __restrict__ dst) {
    int e = blockIdx.x * blockDim.x + threadIdx.x;
    if (e >= N_EDGES) return;
    int d = dst[e];
    int p = atomicAdd(&g_pos[d], 1);
    g_srcs[p] = src[e];
}

// ---------------------------------------------------------------------------
// Layer-0 GEMM:  raw[N,64] = X[N,128] @ W[128,64]
// Epilogue (pre-scale domain): hwS = raw * dinv[n];  agg = hwS  (self-term).
// 64 nodes/block, K staged in two 64-chunks (smem 49.4KB -> 4 blocks/SM).
// ---------------------------------------------------------------------------
__global__ void __launch_bounds__(256)
gemm0_kernel(const float* __restrict__ X, const float* __restrict__ W) {
    const int K = 128;
    const int KC = 64;                 // K-chunk
    extern __shared__ float sm[];
    float* Ws = sm;                    // 128*64 = 32KB
    float* Xs = sm + K * 64;           // 64*65  = 16.64KB (one chunk)

    const int tid = threadIdx.x;
    const int n0  = blockIdx.x * 64;

    for (int i = tid; i < K * 64 / 4; i += 256)
        *(float4*)&Ws[i * 4] = *(const float4*)&W[i * 4];

    const int lane = tid & 31;
    const int warp = tid >> 5;
    const int og   = warp * 8;

    float acc[2][8];
#pragma unroll
    for (int r = 0; r < 2; r++)
#pragma unroll
        for (int j = 0; j < 8; j++) acc[r][j] = 0.f;

    const float* xr0 = &Xs[(lane +  0) * (KC + 1)];
    const float* xr1 = &Xs[(lane + 32) * (KC + 1)];

#pragma unroll
    for (int ck = 0; ck < 2; ck++) {
        __syncthreads();               // previous chunk's compute done
        for (int i = tid; i < 64 * KC / 4; i += 256) {
            int r = i / (KC / 4), c4 = i - r * (KC / 4);
            int n = n0 + r;
            float4 xv = make_float4(0.f, 0.f, 0.f, 0.f);
            if (n < N_NODES) xv = *(const float4*)&X[(size_t)n * K + ck * KC + c4 * 4];
            float* xp = &Xs[r * (KC + 1) + c4 * 4];
            xp[0] = xv.x; xp[1] = xv.y; xp[2] = xv.z; xp[3] = xv.w;
        }
        __syncthreads();

#pragma unroll 4
        for (int k = 0; k < KC; k++) {
            const float4 wa = *(const float4*)&Ws[(ck * KC + k) * 64 + og];
            const float4 wb = *(const float4*)&Ws[(ck * KC + k) * 64 + og + 4];
            float xv;
#define DO_ROW(r, xp)                                                        \
            xv = xp[k];                                                      \
            acc[r][0] += xv * wa.x; acc[r][1] += xv * wa.y;                  \
            acc[r][2] += xv * wa.z; acc[r][3] += xv * wa.w;                  \
            acc[r][4] += xv * wb.x; acc[r][5] += xv * wb.y;                  \
            acc[r][6] += xv * wb.z; acc[r][7] += xv * wb.w;
            DO_ROW(0, xr0) DO_ROW(1, xr1)
#undef DO_ROW
        }
    }

#pragma unroll
    for (int r = 0; r < 2; r++) {
        int n = n0 + lane + 32 * r;
        if (n >= N_NODES) continue;
        float dn = g_dinv[n];
        float* op = g_hw  + (size_t)n * 64 + og;
        float* ap = g_agg + (size_t)n * 64 + og;
        float4 o0 = make_float4(acc[r][0] * dn, acc[r][1] * dn, acc[r][2] * dn, acc[r][3] * dn);
        float4 o1 = make_float4(acc[r][4] * dn, acc[r][5] * dn, acc[r][6] * dn, acc[r][7] * dn);
        *(float4*)op       = o0;
        *(float4*)(op + 4) = o1;
        *(float4*)ap       = o0;        // self-term init (pre-scale domain)
        *(float4*)(ap + 4) = o1;
    }
}

// ---------------------------------------------------------------------------
// Fused dual GEMM for layers 1.. : input h computed on the fly:
//   MODE 0:  x = relu(agg*dinv[n] + bias_prev)
//   MODE 1:  x = relu(agg*dinv[n] + bias_prev) + hs
// conv: raw = x @ Wc;  hwS = raw*dinv;  agg = hwS     (overwrites agg)
// skip: g_hs = x @ Wsk + bs                           (overwrites hs)
// ---------------------------------------------------------------------------
template <int MODE>
__global__ void __launch_bounds__(256)
gemm_dual_kernel(const float* __restrict__ Wc, const float* __restrict__ bias_prev,
                 const float* __restrict__ Wsk, const float* __restrict__ bs) {
    const int K = 64;
    extern __shared__ float sm[];
    float* Wcs = sm;                    // 64*64 = 16KB
    float* Wss = sm + K * 64;           // 64*64 = 16KB
    float* Xs  = sm + 2 * K * 64;       // 64*65 = 16.64KB

    const int tid = threadIdx.x;
    const int n0  = blockIdx.x * 64;

    for (int i = tid; i < K * 64 / 4; i += 256) {
        *(float4*)&Wcs[i * 4] = *(const float4*)&Wc[i * 4];
        *(float4*)&Wss[i * 4] = *(const float4*)&Wsk[i * 4];
    }
    for (int i = tid; i < 64 * K / 4; i += 256) {
        int r = i / (K / 4), c4 = i - r * (K / 4);
        int n = n0 + r;
        float4 xv = make_float4(0.f, 0.f, 0.f, 0.f);
        if (n < N_NODES) {
            float dn = g_dinv[n];
            float4 bb = *(const float4*)&bias_prev[c4 * 4];
            float4 a = *(const float4*)&g_agg[(size_t)n * K + c4 * 4];
            xv = make_float4(fmaxf(fmaf(a.x, dn, bb.x), 0.f),
                             fmaxf(fmaf(a.y, dn, bb.y), 0.f),
                             fmaxf(fmaf(a.z, dn, bb.z), 0.f),
                             fmaxf(fmaf(a.w, dn, bb.w), 0.f));
            if (MODE == 1) {
                float4 s = *(const float4*)&g_hs[(size_t)n * K + c4 * 4];
                xv.x += s.x; xv.y += s.y; xv.z += s.z; xv.w += s.w;
            }
        }
        float* xp = &Xs[r * (K + 1) + c4 * 4];
        xp[0] = xv.x; xp[1] = xv.y; xp[2] = xv.z; xp[3] = xv.w;
    }
    __syncthreads();

    const int lane = tid & 31;
    const int warp = tid >> 5;
    const int og   = warp * 8;

    float accC[2][8], accS[2][8];
#pragma unroll
    for (int r = 0; r < 2; r++)
#pragma unroll
        for (int j = 0; j < 8; j++) { accC[r][j] = 0.f; accS[r][j] = 0.f; }

    const float* xr0 = &Xs[(lane +  0) * (K + 1)];
    const float* xr1 = &Xs[(lane + 32) * (K + 1)];

#pragma unroll 2
    for (int k = 0; k < K; k++) {
        const float4 ca = *(const float4*)&Wcs[k * 64 + og];
        const float4 cb = *(const float4*)&Wcs[k * 64 + og + 4];
        const float4 sa = *(const float4*)&Wss[k * 64 + og];
        const float4 sb = *(const float4*)&Wss[k * 64 + og + 4];
        float xv;
#define DO_ROW(r, xp)                                                          \
        xv = xp[k];                                                            \
        accC[r][0] += xv * ca.x; accC[r][1] += xv * ca.y;                      \
        accC[r][2] += xv * ca.z; accC[r][3] += xv * ca.w;                      \
        accC[r][4] += xv * cb.x; accC[r][5] += xv * cb.y;                      \
        accC[r][6] += xv * cb.z; accC[r][7] += xv * cb.w;                      \
        accS[r][0] += xv * sa.x; accS[r][1] += xv * sa.y;                      \
        accS[r][2] += xv * sa.z; accS[r][3] += xv * sa.w;                      \
        accS[r][4] += xv * sb.x; accS[r][5] += xv * sb.y;                      \
        accS[r][6] += xv * sb.z; accS[r][7] += xv * sb.w;
        DO_ROW(0, xr0) DO_ROW(1, xr1)
#undef DO_ROW
    }

    const float4 bsa = *(const float4*)&bs[og];
    const float4 bsb = *(const float4*)&bs[og + 4];

#pragma unroll
    for (int r = 0; r < 2; r++) {
        int n = n0 + lane + 32 * r;
        if (n >= N_NODES) continue;
        float dn = g_dinv[n];
        float* op = g_hw  + (size_t)n * 64 + og;
        float* ap = g_agg + (size_t)n * 64 + og;
        float* sp = g_hs  + (size_t)n * 64 + og;
        float4 o0 = make_float4(accC[r][0] * dn, accC[r][1] * dn, accC[r][2] * dn, accC[r][3] * dn);
        float4 o1 = make_float4(accC[r][4] * dn, accC[r][5] * dn, accC[r][6] * dn, accC[r][7] * dn);
        *(float4*)op       = o0;
        *(float4*)(op + 4) = o1;
        *(float4*)ap       = o0;        // self-term init (pre-scale domain)
        *(float4*)(ap + 4) = o1;
        *(float4*)sp       = make_float4(accS[r][0] + bsa.x, accS[r][1] + bsa.y,
                                         accS[r][2] + bsa.z, accS[r][3] + bsa.w);
        *(float4*)(sp + 4) = make_float4(accS[r][4] + bsb.x, accS[r][5] + bsb.y,
                                         accS[r][6] + bsb.z, accS[r][7] + bsb.w);
    }
}

// ---------------------------------------------------------------------------
// CSR edge aggregation (pre-scale domain): for each dst d,
//   agg[d] += sum_{s in srcs(d)} hw[s]
// 8 threads per dst, each owning 8 contiguous floats; register accumulation,
// ONE read-modify-write of agg per dst -> no atomics, no red traffic.
// ---------------------------------------------------------------------------
__global__ void __launch_bounds__(256) edge_csr_kernel() {
    int gid = blockIdx.x * blockDim.x + threadIdx.x;
    int d = gid >> 3;
    if (d >= N_NODES) return;
    int q = (gid & 7) << 3;            // 0,8,...,56
    int st = __ldg(&g_off[d]);
    int en = __ldg(&g_off[d + 1]);

    float* ap = &g_agg[(size_t)d * 64 + q];
    float4 a0 = *(float4*)ap;          // self term (from GEMM epilogue)
    float4 a1 = *(float4*)(ap + 4);

    int e = st;
    for (; e + 1 < en; e += 2) {       // 2-way unroll for MLP
        int s0 = __ldg(&g_srcs[e]);
        int s1 = __ldg(&g_srcs[e + 1]);
        const float* h0 = &g_hw[(size_t)s0 * 64 + q];
        const float* h1 = &g_hw[(size_t)s1 * 64 + q];
        float4 u0 = __ldg((const float4*)h0);
        float4 u1 = __ldg((const float4*)(h0 + 4));
        float4 w0 = __ldg((const float4*)h1);
        float4 w1 = __ldg((const float4*)(h1 + 4));
        a0.x += u0.x + w0.x; a0.y += u0.y + w0.y;
        a0.z += u0.z + w0.z; a0.w += u0.w + w0.w;
        a1.x += u1.x + w1.x; a1.y += u1.y + w1.y;
        a1.z += u1.z + w1.z; a1.w += u1.w + w1.w;
    }
    if (e < en) {
        int s0 = __ldg(&g_srcs[e]);
        const float* h0 = &g_hw[(size_t)s0 * 64 + q];
        float4 u0 = __ldg((const float4*)h0);
        float4 u1 = __ldg((const float4*)(h0 + 4));
        a0.x += u0.x; a0.y += u0.y; a0.z += u0.z; a0.w += u0.w;
        a1.x += u1.x; a1.y += u1.y; a1.z += u1.z; a1.w += u1.w;
    }

    *(float4*)ap       = a0;
    *(float4*)(ap + 4) = a1;
}

// global mean-pool accumulation; h = relu(agg*dinv + bias2) + hs on the fly
__global__ void pool_kernel(const int* __restrict__ b, const float* __restrict__ bias2) {
    int gid = blockIdx.x * blockDim.x + threadIdx.x;
    int n = gid >> 4;
    if (n >= N_NODES) return;
    int q = (gid & 15) << 2;
    int g = __ldg(&b[n]);
    float dn = __ldg(&g_dinv[n]);
    float4 bb = *(const float4*)&bias2[q];
    float4 a = __ldg((const float4*)&g_agg[(size_t)n * 64 + q]);
    float4 s = __ldg((const float4*)&g_hs[(size_t)n * 64 + q]);
    float4 v = make_float4(fmaxf(fmaf(a.x, dn, bb.x), 0.f) + s.x,
                           fmaxf(fmaf(a.y, dn, bb.y), 0.f) + s.y,
                           fmaxf(fmaf(a.z, dn, bb.z), 0.f) + s.z,
                           fmaxf(fmaf(a.w, dn, bb.w), 0.f) + s.w);
    float* p = &g_pool[(size_t)g * 64 + q];
    asm volatile("red.global.add.v4.f32 [%0], {%1, %2, %3, %4};"
                 :: "l"(p), "f"(v.x), "f"(v.y), "f"(v.z), "f"(v.w) : "memory");
    if (q == 0) atomicAdd(&g_cnt[g], 1.0f);
}

// MLP head: one warp per graph
__global__ void head_kernel(const float* __restrict__ lin1W, const float* __restrict__ lin1b,
                            const float* __restrict__ lin2W, const float* __restrict__ lin2b,
                            float* __restrict__ outp) {
    int gid  = blockIdx.x * blockDim.x + threadIdx.x;
    int g    = gid >> 5;
    int lane = gid & 31;
    if (g >= N_GRAPHS) return;
    float rc = 1.0f / fmaxf(g_cnt[g], 1.0f);
    float acc = 0.f;
#pragma unroll
    for (int k = 0; k < 64; k++)
        acc += g_pool[(size_t)g * 64 + k] * lin1W[k * 32 + lane];
    acc = fmaxf(fmaf(acc, rc, lin1b[lane]), 0.f);
    float part = acc * lin2W[lane];
#pragma unroll
    for (int off = 16; off; off >>= 1)
        part += __shfl_down_sync(0xffffffffu, part, off);
    if (lane == 0) outp[g] = part + lin2b[0];
}

// ---------------------------------------------------------------------------
extern "C" void kernel_launch(void* const* d_in, const int* in_sizes, int n_in,
                              void* d_out, int out_size) {
    const float* x     = (const float*)d_in[0];
    const int*   e_idx = (const int*)  d_in[1];
    const int*   src   = e_idx;
    const int*   dst   = e_idx + N_EDGES;
    const int*   b     = (const int*)  d_in[2];
    const float* w0    = (const float*)d_in[3];
    const float* b0    = (const float*)d_in[4];
    const float* convW = (const float*)d_in[5];
    const float* convB = (const float*)d_in[6];
    const float* skipW = (const float*)d_in[7];
    const float* skipB = (const float*)d_in[8];
    const float* lin1W = (const float*)d_in[9];
    const float* lin1b = (const float*)d_in[10];
    const float* lin2W = (const float*)d_in[11];
    const float* lin2b = (const float*)d_in[12];
    float* out = (float*)d_out;

    int* cnt_i;
    float *pool, *cnt;
    cudaGetSymbolAddress((void**)&cnt_i, g_cnt_i);
    cudaGetSymbolAddress((void**)&pool,  g_pool);
    cudaGetSymbolAddress((void**)&cnt,   g_cnt);

    const int SMEM0 = (128 * 64 + 64 * 65) * 4;     // 49408 B
    const int SMEMD = (2 * 64 * 64 + 64 * 65) * 4;  // 49408 B
    cudaFuncSetAttribute(gemm0_kernel, cudaFuncAttributeMaxDynamicSharedMemorySize, SMEM0);
    cudaFuncSetAttribute(gemm_dual_kernel<0>, cudaFuncAttributeMaxDynamicSharedMemorySize, SMEMD);
    cudaFuncSetAttribute(gemm_dual_kernel<1>, cudaFuncAttributeMaxDynamicSharedMemorySize, SMEMD);

    const int NB_NODE  = (N_NODES + 255) / 256;
    const int NB_GEMM  = (N_NODES + 63) / 64;          // 1563
    const int NB_CSR   = (N_NODES * 8 + 255) / 256;    // 3125
    const int NB_HV    = (N_NODES * 16 + 255) / 256;   // 6250
    const int NB_EDGE  = (N_EDGES + 255) / 256;

    // CSR prep: histogram -> dinv -> scan -> scatter
    zero_i_kernel<<<NB_NODE, 256>>>(cnt_i, N_NODES);
    hist_kernel<<<NB_EDGE, 256>>>(dst);
    dinv_kernel<<<NB_NODE, 256>>>();
    scan_kernel<<<1, 1024>>>();
    scatter_kernel<<<NB_EDGE, 256>>>(src, dst);

    // layer 0: agg0 = (x@w0)*dinv (self) + CSR-gathered neighbor messages
    gemm0_kernel<<<NB_GEMM, 256, SMEM0>>>(x, w0);
    edge_csr_kernel<<<NB_CSR, 256>>>();

    // layer 1: x1 = relu(agg0*dinv + b0); conv+skip fused GEMM, then edge pass
    gemm_dual_kernel<0><<<NB_GEMM, 256, SMEMD>>>(convW, b0, skipW, skipB);
    edge_csr_kernel<<<NB_CSR, 256>>>();

    // layer 2: x2 = relu(agg1*dinv + convB[0]) + hs1; fused GEMM, edge pass
    gemm_dual_kernel<1><<<NB_GEMM, 256, SMEMD>>>(convW + 64 * 64, convB,
                                                 skipW + 64 * 64, skipB + 64);
    edge_csr_kernel<<<NB_CSR, 256>>>();

    // global mean pool (h = relu(agg2*dinv + convB[1]) + hs2) + MLP head
    zero_f_kernel<<<(N_GRAPHS * 64 + 255) / 256, 256>>>(pool, N_GRAPHS * 64);
    zero_f_kernel<<<(N_GRAPHS + 255) / 256, 256>>>(cnt, N_GRAPHS);
    pool_kernel<<<NB_HV, 256>>>(b, convB + 64);
    head_kernel<<<(N_GRAPHS * 32 + 255) / 256, 256>>>(lin1W, lin1b, lin2W, lin2b, out);
}

// round 15
// speedup vs baseline: 1.4169x; 1.4169x over previous
#include <cuda_runtime.h>
#include <cuda_bf16.h>
#include <cstddef>

#define N_NODES 100000
#define N_EDGES 1600000
#define N_FEAT  128
#define H_CH    64
#define N_GRAPHS 4096

// ---------------------------------------------------------------------------
// Scratch (device globals; no allocation allowed)
// ---------------------------------------------------------------------------
__device__ int   g_cnt_i[N_NODES];                  // per-dst edge count
__device__ int   g_off  [N_NODES];                  // CSR range start per dst
__device__ int   g_pos  [N_NODES];                  // scatter cursors
__device__ int   g_ctr;                             // global range allocator
__device__ int   g_srcs [N_EDGES];                  // src indices grouped by dst
__device__ float g_dinv [N_NODES];
__device__ float g_hw  [(size_t)N_NODES * H_CH];    // pre-scaled message: (h@W)*dinv[n]
__device__ float g_agg [(size_t)N_NODES * H_CH];    // pre-scale-domain accumulator
__device__ float g_hs  [(size_t)N_NODES * H_CH];    // skip-path result
__device__ float g_pool[(size_t)N_GRAPHS * H_CH];
__device__ float g_cnt [N_GRAPHS];

// ---------------------------------------------------------------------------
// Prep kernels: zero -> histogram -> dinv -> offsets (warp-agg atomic) -> scatter
// ---------------------------------------------------------------------------
__global__ void zero_f_kernel(float* __restrict__ p, int n) {
    int i = blockIdx.x * blockDim.x + threadIdx.x;
    if (i < n) p[i] = 0.f;
}

__global__ void prep_zero_kernel() {
    int i = blockIdx.x * blockDim.x + threadIdx.x;
    if (i < N_NODES) g_cnt_i[i] = 0;
    if (i == 0) g_ctr = 0;
}

__global__ void hist_kernel(const int* __restrict__ dst) {
    int i = blockIdx.x * blockDim.x + threadIdx.x;
    if (i < N_EDGES) atomicAdd(&g_cnt_i[dst[i]], 1);
}

__global__ void dinv_kernel() {
    int i = blockIdx.x * blockDim.x + threadIdx.x;
    if (i < N_NODES) g_dinv[i] = rsqrtf((float)g_cnt_i[i] + 1.0f);
}

// Warp-aggregated range allocation: each dst gets a contiguous [start,start+cnt)
// range; ranges need NOT be monotonic across dsts, only disjoint and covering.
// One atomicAdd per warp (3125 total).
__global__ void offsets_kernel() {
    int i = blockIdx.x * blockDim.x + threadIdx.x;
    int lane = threadIdx.x & 31;
    int c = (i < N_NODES) ? g_cnt_i[i] : 0;

    // warp inclusive scan of c
    int incl = c;
#pragma unroll
    for (int off = 1; off < 32; off <<= 1) {
        int v = __shfl_up_sync(0xffffffffu, incl, off);
        if (lane >= off) incl += v;
    }
    int total = __shfl_sync(0xffffffffu, incl, 31);
    int base = 0;
    if (lane == 0 && total > 0) base = atomicAdd(&g_ctr, total);
    base = __shfl_sync(0xffffffffu, base, 0);

    if (i < N_NODES) {
        int start = base + incl - c;
        g_off[i] = start;
        g_pos[i] = start;
    }
}

__global__ void scatter_kernel(const int* __restrict__ src, const int* __restrict__ dst) {
    int e = blockIdx.x * blockDim.x + threadIdx.x;
    if (e >= N_EDGES) return;
    int d = dst[e];
    int p = atomicAdd(&g_pos[d], 1);
    g_srcs[p] = src[e];
}

// ---------------------------------------------------------------------------
// Layer-0 GEMM:  raw[N,64] = X[N,128] @ W[128,64]
// Epilogue (pre-scale domain): hwS = raw * dinv[n];  agg = hwS  (self-term).
// 64 nodes/block, K staged in two 64-chunks (smem 49.4KB -> 4 blocks/SM).
// ---------------------------------------------------------------------------
__global__ void __launch_bounds__(256)
gemm0_kernel(const float* __restrict__ X, const float* __restrict__ W) {
    const int K = 128;
    const int KC = 64;                 // K-chunk
    extern __shared__ float sm[];
    float* Ws = sm;                    // 128*64 = 32KB
    float* Xs = sm + K * 64;           // 64*65  = 16.64KB (one chunk)

    const int tid = threadIdx.x;
    const int n0  = blockIdx.x * 64;

    for (int i = tid; i < K * 64 / 4; i += 256)
        *(float4*)&Ws[i * 4] = *(const float4*)&W[i * 4];

    const int lane = tid & 31;
    const int warp = tid >> 5;
    const int og   = warp * 8;

    float acc[2][8];
#pragma unroll
    for (int r = 0; r < 2; r++)
#pragma unroll
        for (int j = 0; j < 8; j++) acc[r][j] = 0.f;

    const float* xr0 = &Xs[(lane +  0) * (KC + 1)];
    const float* xr1 = &Xs[(lane + 32) * (KC + 1)];

#pragma unroll
    for (int ck = 0; ck < 2; ck++) {
        __syncthreads();               // previous chunk's compute done
        for (int i = tid; i < 64 * KC / 4; i += 256) {
            int r = i / (KC / 4), c4 = i - r * (KC / 4);
            int n = n0 + r;
            float4 xv = make_float4(0.f, 0.f, 0.f, 0.f);
            if (n < N_NODES) xv = *(const float4*)&X[(size_t)n * K + ck * KC + c4 * 4];
            float* xp = &Xs[r * (KC + 1) + c4 * 4];
            xp[0] = xv.x; xp[1] = xv.y; xp[2] = xv.z; xp[3] = xv.w;
        }
        __syncthreads();

#pragma unroll 4
        for (int k = 0; k < KC; k++) {
            const float4 wa = *(const float4*)&Ws[(ck * KC + k) * 64 + og];
            const float4 wb = *(const float4*)&Ws[(ck * KC + k) * 64 + og + 4];
            float xv;
#define DO_ROW(r, xp)                                                        \
            xv = xp[k];                                                      \
            acc[r][0] += xv * wa.x; acc[r][1] += xv * wa.y;                  \
            acc[r][2] += xv * wa.z; acc[r][3] += xv * wa.w;                  \
            acc[r][4] += xv * wb.x; acc[r][5] += xv * wb.y;                  \
            acc[r][6] += xv * wb.z; acc[r][7] += xv * wb.w;
            DO_ROW(0, xr0) DO_ROW(1, xr1)
#undef DO_ROW
        }
    }

#pragma unroll
    for (int r = 0; r < 2; r++) {
        int n = n0 + lane + 32 * r;
        if (n >= N_NODES) continue;
        float dn = g_dinv[n];
        float* op = g_hw  + (size_t)n * 64 + og;
        float* ap = g_agg + (size_t)n * 64 + og;
        float4 o0 = make_float4(acc[r][0] * dn, acc[r][1] * dn, acc[r][2] * dn, acc[r][3] * dn);
        float4 o1 = make_float4(acc[r][4] * dn, acc[r][5] * dn, acc[r][6] * dn, acc[r][7] * dn);
        *(float4*)op       = o0;
        *(float4*)(op + 4) = o1;
        *(float4*)ap       = o0;        // self-term init (pre-scale domain)
        *(float4*)(ap + 4) = o1;
    }
}

// ---------------------------------------------------------------------------
// Fused dual GEMM for layers 1.. : input h computed on the fly:
//   MODE 0:  x = relu(agg*dinv[n] + bias_prev)
//   MODE 1:  x = relu(agg*dinv[n] + bias_prev) + hs
// conv: raw = x @ Wc;  hwS = raw*dinv;  agg = hwS     (overwrites agg)
// skip: g_hs = x @ Wsk + bs                           (overwrites hs)
// ---------------------------------------------------------------------------
template <int MODE>
__global__ void __launch_bounds__(256)
gemm_dual_kernel(const float* __restrict__ Wc, const float* __restrict__ bias_prev,
                 const float* __restrict__ Wsk, const float* __restrict__ bs) {
    const int K = 64;
    extern __shared__ float sm[];
    float* Wcs = sm;                    // 64*64 = 16KB
    float* Wss = sm + K * 64;           // 64*64 = 16KB
    float* Xs  = sm + 2 * K * 64;       // 64*65 = 16.64KB

    const int tid = threadIdx.x;
    const int n0  = blockIdx.x * 64;

    for (int i = tid; i < K * 64 / 4; i += 256) {
        *(float4*)&Wcs[i * 4] = *(const float4*)&Wc[i * 4];
        *(float4*)&Wss[i * 4] = *(const float4*)&Wsk[i * 4];
    }
    for (int i = tid; i < 64 * K / 4; i += 256) {
        int r = i / (K / 4), c4 = i - r * (K / 4);
        int n = n0 + r;
        float4 xv = make_float4(0.f, 0.f, 0.f, 0.f);
        if (n < N_NODES) {
            float dn = g_dinv[n];
            float4 bb = *(const float4*)&bias_prev[c4 * 4];
            float4 a = *(const float4*)&g_agg[(size_t)n * K + c4 * 4];
            xv = make_float4(fmaxf(fmaf(a.x, dn, bb.x), 0.f),
                             fmaxf(fmaf(a.y, dn, bb.y), 0.f),
                             fmaxf(fmaf(a.z, dn, bb.z), 0.f),
                             fmaxf(fmaf(a.w, dn, bb.w), 0.f));
            if (MODE == 1) {
                float4 s = *(const float4*)&g_hs[(size_t)n * K + c4 * 4];
                xv.x += s.x; xv.y += s.y; xv.z += s.z; xv.w += s.w;
            }
        }
        float* xp = &Xs[r * (K + 1) + c4 * 4];
        xp[0] = xv.x; xp[1] = xv.y; xp[2] = xv.z; xp[3] = xv.w;
    }
    __syncthreads();

    const int lane = tid & 31;
    const int warp = tid >> 5;
    const int og   = warp * 8;

    float accC[2][8], accS[2][8];
#pragma unroll
    for (int r = 0; r < 2; r++)
#pragma unroll
        for (int j = 0; j < 8; j++) { accC[r][j] = 0.f; accS[r][j] = 0.f; }

    const float* xr0 = &Xs[(lane +  0) * (K + 1)];
    const float* xr1 = &Xs[(lane + 32) * (K + 1)];

#pragma unroll 2
    for (int k = 0; k < K; k++) {
        const float4 ca = *(const float4*)&Wcs[k * 64 + og];
        const float4 cb = *(const float4*)&Wcs[k * 64 + og + 4];
        const float4 sa = *(const float4*)&Wss[k * 64 + og];
        const float4 sb = *(const float4*)&Wss[k * 64 + og + 4];
        float xv;
#define DO_ROW(r, xp)                                                          \
        xv = xp[k];                                                            \
        accC[r][0] += xv * ca.x; accC[r][1] += xv * ca.y;                      \
        accC[r][2] += xv * ca.z; accC[r][3] += xv * ca.w;                      \
        accC[r][4] += xv * cb.x; accC[r][5] += xv * cb.y;                      \
        accC[r][6] += xv * cb.z; accC[r][7] += xv * cb.w;                      \
        accS[r][0] += xv * sa.x; accS[r][1] += xv * sa.y;                      \
        accS[r][2] += xv * sa.z; accS[r][3] += xv * sa.w;                      \
        accS[r][4] += xv * sb.x; accS[r][5] += xv * sb.y;                      \
        accS[r][6] += xv * sb.z; accS[r][7] += xv * sb.w;
        DO_ROW(0, xr0) DO_ROW(1, xr1)
#undef DO_ROW
    }

    const float4 bsa = *(const float4*)&bs[og];
    const float4 bsb = *(const float4*)&bs[og + 4];

#pragma unroll
    for (int r = 0; r < 2; r++) {
        int n = n0 + lane + 32 * r;
        if (n >= N_NODES) continue;
        float dn = g_dinv[n];
        float* op = g_hw  + (size_t)n * 64 + og;
        float* ap = g_agg + (size_t)n * 64 + og;
        float* sp = g_hs  + (size_t)n * 64 + og;
        float4 o0 = make_float4(accC[r][0] * dn, accC[r][1] * dn, accC[r][2] * dn, accC[r][3] * dn);
        float4 o1 = make_float4(accC[r][4] * dn, accC[r][5] * dn, accC[r][6] * dn, accC[r][7] * dn);
        *(float4*)op       = o0;
        *(float4*)(op + 4) = o1;
        *(float4*)ap       = o0;        // self-term init (pre-scale domain)
        *(float4*)(ap + 4) = o1;
        *(float4*)sp       = make_float4(accS[r][0] + bsa.x, accS[r][1] + bsa.y,
                                         accS[r][2] + bsa.z, accS[r][3] + bsa.w);
        *(float4*)(sp + 4) = make_float4(accS[r][4] + bsb.x, accS[r][5] + bsb.y,
                                         accS[r][6] + bsb.z, accS[r][7] + bsb.w);
    }
}

// ---------------------------------------------------------------------------
// CSR edge aggregation (pre-scale domain): for each dst d,
//   agg[d] += sum over its range [off[d], off[d]+cnt[d]) of hw[srcs[e]]
// 8 threads per dst, each owning 8 contiguous floats; register accumulation,
// ONE read-modify-write of agg per dst -> no atomics, no red traffic.
// ---------------------------------------------------------------------------
__global__ void __launch_bounds__(256) edge_csr_kernel() {
    int gid = blockIdx.x * blockDim.x + threadIdx.x;
    int d = gid >> 3;
    if (d >= N_NODES) return;
    int q = (gid & 7) << 3;            // 0,8,...,56
    int st = __ldg(&g_off[d]);
    int en = st + __ldg(&g_cnt_i[d]);

    float* ap = &g_agg[(size_t)d * 64 + q];
    float4 a0 = *(float4*)ap;          // self term (from GEMM epilogue)
    float4 a1 = *(float4*)(ap + 4);

    int e = st;
    for (; e + 1 < en; e += 2) {       // 2-way unroll for MLP
        int s0 = __ldg(&g_srcs[e]);
        int s1 = __ldg(&g_srcs[e + 1]);
        const float* h0 = &g_hw[(size_t)s0 * 64 + q];
        const float* h1 = &g_hw[(size_t)s1 * 64 + q];
        float4 u0 = __ldg((const float4*)h0);
        float4 u1 = __ldg((const float4*)(h0 + 4));
        float4 w0 = __ldg((const float4*)h1);
        float4 w1 = __ldg((const float4*)(h1 + 4));
        a0.x += u0.x + w0.x; a0.y += u0.y + w0.y;
        a0.z += u0.z + w0.z; a0.w += u0.w + w0.w;
        a1.x += u1.x + w1.x; a1.y += u1.y + w1.y;
        a1.z += u1.z + w1.z; a1.w += u1.w + w1.w;
    }
    if (e < en) {
        int s0 = __ldg(&g_srcs[e]);
        const float* h0 = &g_hw[(size_t)s0 * 64 + q];
        float4 u0 = __ldg((const float4*)h0);
        float4 u1 = __ldg((const float4*)(h0 + 4));
        a0.x += u0.x; a0.y += u0.y; a0.z += u0.z; a0.w += u0.w;
        a1.x += u1.x; a1.y += u1.y; a1.z += u1.z; a1.w += u1.w;
    }

    *(float4*)ap       = a0;
    *(float4*)(ap + 4) = a1;
}

// global mean-pool accumulation; h = relu(agg*dinv + bias2) + hs on the fly
__global__ void pool_kernel(const int* __restrict__ b, const float* __restrict__ bias2) {
    int gid = blockIdx.x * blockDim.x + threadIdx.x;
    int n = gid >> 4;
    if (n >= N_NODES) return;
    int q = (gid & 15) << 2;
    int g = __ldg(&b[n]);
    float dn = __ldg(&g_dinv[n]);
    float4 bb = *(const float4*)&bias2[q];
    float4 a = __ldg((const float4*)&g_agg[(size_t)n * 64 + q]);
    float4 s = __ldg((const float4*)&g_hs[(size_t)n * 64 + q]);
    float4 v = make_float4(fmaxf(fmaf(a.x, dn, bb.x), 0.f) + s.x,
                           fmaxf(fmaf(a.y, dn, bb.y), 0.f) + s.y,
                           fmaxf(fmaf(a.z, dn, bb.z), 0.f) + s.z,
                           fmaxf(fmaf(a.w, dn, bb.w), 0.f) + s.w);
    float* p = &g_pool[(size_t)g * 64 + q];
    asm volatile("red.global.add.v4.f32 [%0], {%1, %2, %3, %4};"
                 :: "l"(p), "f"(v.x), "f"(v.y), "f"(v.z), "f"(v.w) : "memory");
    if (q == 0) atomicAdd(&g_cnt[g], 1.0f);
}

// MLP head: one warp per graph
__global__ void head_kernel(const float* __restrict__ lin1W, const float* __restrict__ lin1b,
                            const float* __restrict__ lin2W, const float* __restrict__ lin2b,
                            float* __restrict__ outp) {
    int gid  = blockIdx.x * blockDim.x + threadIdx.x;
    int g    = gid >> 5;
    int lane = gid & 31;
    if (g >= N_GRAPHS) return;
    float rc = 1.0f / fmaxf(g_cnt[g], 1.0f);
    float acc = 0.f;
#pragma unroll
    for (int k = 0; k < 64; k++)
        acc += g_pool[(size_t)g * 64 + k] * lin1W[k * 32 + lane];
    acc = fmaxf(fmaf(acc, rc, lin1b[lane]), 0.f);
    float part = acc * lin2W[lane];
#pragma unroll
    for (int off = 16; off; off >>= 1)
        part += __shfl_down_sync(0xffffffffu, part, off);
    if (lane == 0) outp[g] = part + lin2b[0];
}

// ---------------------------------------------------------------------------
extern "C" void kernel_launch(void* const* d_in, const int* in_sizes, int n_in,
                              void* d_out, int out_size) {
    const float* x     = (const float*)d_in[0];
    const int*   e_idx = (const int*)  d_in[1];
    const int*   src   = e_idx;
    const int*   dst   = e_idx + N_EDGES;
    const int*   b     = (const int*)  d_in[2];
    const float* w0    = (const float*)d_in[3];
    const float* b0    = (const float*)d_in[4];
    const float* convW = (const float*)d_in[5];
    const float* convB = (const float*)d_in[6];
    const float* skipW = (const float*)d_in[7];
    const float* skipB = (const float*)d_in[8];
    const float* lin1W = (const float*)d_in[9];
    const float* lin1b = (const float*)d_in[10];
    const float* lin2W = (const float*)d_in[11];
    const float* lin2b = (const float*)d_in[12];
    float* out = (float*)d_out;

    float *pool, *cnt;
    cudaGetSymbolAddress((void**)&pool, g_pool);
    cudaGetSymbolAddress((void**)&cnt,  g_cnt);

    const int SMEM0 = (128 * 64 + 64 * 65) * 4;     // 49408 B
    const int SMEMD = (2 * 64 * 64 + 64 * 65) * 4;  // 49408 B
    cudaFuncSetAttribute(gemm0_kernel, cudaFuncAttributeMaxDynamicSharedMemorySize, SMEM0);
    cudaFuncSetAttribute(gemm_dual_kernel<0>, cudaFuncAttributeMaxDynamicSharedMemorySize, SMEMD);
    cudaFuncSetAttribute(gemm_dual_kernel<1>, cudaFuncAttributeMaxDynamicSharedMemorySize, SMEMD);

    const int NB_NODE  = (N_NODES + 255) / 256;
    const int NB_GEMM  = (N_NODES + 63) / 64;          // 1563
    const int NB_CSR   = (N_NODES * 8 + 255) / 256;    // 3125
    const int NB_HV    = (N_NODES * 16 + 255) / 256;   // 6250
    const int NB_EDGE  = (N_EDGES + 255) / 256;

    // CSR prep: zero -> histogram -> dinv -> warp-agg offsets -> scatter
    prep_zero_kernel<<<NB_NODE, 256>>>();
    hist_kernel<<<NB_EDGE, 256>>>(dst);
    dinv_kernel<<<NB_NODE, 256>>>();
    offsets_kernel<<<NB_NODE, 256>>>();
    scatter_kernel<<<NB_EDGE, 256>>>(src, dst);

    // layer 0: agg0 = (x@w0)*dinv (self) + CSR-gathered neighbor messages
    gemm0_kernel<<<NB_GEMM, 256, SMEM0>>>(x, w0);
    edge_csr_kernel<<<NB_CSR, 256>>>();

    // layer 1: x1 = relu(agg0*dinv + b0); conv+skip fused GEMM, then edge pass
    gemm_dual_kernel<0><<<NB_GEMM, 256, SMEMD>>>(convW, b0, skipW, skipB);
    edge_csr_kernel<<<NB_CSR, 256>>>();

    // layer 2: x2 = relu(agg1*dinv + convB[0]) + hs1; fused GEMM, edge pass
    gemm_dual_kernel<1><<<NB_GEMM, 256, SMEMD>>>(convW + 64 * 64, convB,
                                                 skipW + 64 * 64, skipB + 64);
    edge_csr_kernel<<<NB_CSR, 256>>>();

    // global mean pool (h = relu(agg2*dinv + convB[1]) + hs2) + MLP head
    zero_f_kernel<<<(N_GRAPHS * 64 + 255) / 256, 256>>>(pool, N_GRAPHS * 64);
    zero_f_kernel<<<(N_GRAPHS + 255) / 256, 256>>>(cnt, N_GRAPHS);
    pool_kernel<<<NB_HV, 256>>>(b, convB + 64);
    head_kernel<<<(N_GRAPHS * 32 + 255) / 256, 256>>>(lin1W, lin1b, lin2W, lin2b, out);
}